// round 12
// baseline (speedup 1.0000x reference)
#include <cuda_runtime.h>
#include <cstdint>

#define NH      128
#define NCODES  512
#define NCELLS  65536
#define NCOARSE 4096                   // 16 fine cells per coarse cell
#define XMIN    (-5.75f)
#define XMAX    (5.75f)
#define CW      (11.5f / 65536.0f)
#define INV_CW  (65536.0f / 11.5f)
#define FULLM   0xffffffffu

__device__ __forceinline__ float neg_inf() { return __int_as_float(0xff800000); }
__device__ __forceinline__ float pos_inf() { return __int_as_float(0x7f800000); }

// -------- device scratch (no allocation allowed) --------
__device__ float    g_ksort[NH];        // sorted kink positions (+inf padded)
__device__ float    g_A[129 * NCODES];  // per-interval intercepts
__device__ float    g_B[129 * NCODES];  // per-interval slopes
__device__ float    g_score[NCODES];    // dec_w . emb[c]
__device__ float    g_decb;
__device__ unsigned char g_kinkNear[NCELLS];   // set-only, deterministic per replay
__device__ unsigned short g_cellEnc[NCELLS];   // idx | (bad ? 0x8000 : 0)

// ======== kernel 1 (fused prep) ========
// blocks 0..31  : A/B tables — warp = code, lanes = hidden units (coalesced w2)
// block  32     : sorted kinks + kink-adjacent cell flags + decoder bias
// blocks 33..64 : score[c] = dec_w . emb[c]
__global__ void k_prep(const float* __restrict__ w1, const float* __restrict__ b1,
                       const float* __restrict__ w2, const float* __restrict__ b2,
                       const float* __restrict__ emb, const float* __restrict__ dec_w,
                       const float* __restrict__ dec_b)
{
    int blk = blockIdx.x;
    int t = threadIdx.x;                 // 512 threads
    int lane = t & 31;
    if (blk < 32) {
        // ---- ranks/signs in smem (each block recomputes; cheap) ----
        __shared__ float sw[NH], sb[NH], skv[NH];
        __shared__ int   sR[NH], sS[NH];
        if (t < NH) {
            float w = w1[t], b = b1[t];
            sw[t] = w; sb[t] = b;
            skv[t] = (w != 0.0f) ? (-b / w) : pos_inf();
        }
        __syncthreads();
        if (t < NH) {
            float kv = skv[t];
            int r = 0;
            #pragma unroll 8
            for (int k = 0; k < NH; k++) {
                float o = skv[k];
                r += (o < kv) || (o == kv && k < t);   // unique rank, index tiebreak
            }
            float w = sw[t], b = sb[t];
            sR[t] = (w != 0.0f) ? r : NH;
            sS[t] = (w > 0.0f) ? 1 : ((w < 0.0f) ? -1 : ((b > 0.0f) ? -1 : 1));
        }
        __syncthreads();
        // ---- one warp per code; lane-parallel over hidden units j ----
        int code = blk * 16 + (t >> 5);
        float v[4], vb[4], vw[4];
        int   rk[4], sg[4];
        const float* wr = w2 + code * NH;
        #pragma unroll
        for (int k = 0; k < 4; k++) {
            int j = lane + (k << 5);
            v[k]  = wr[j];               // coalesced: warp reads 128B line
            vb[k] = sb[j];
            vw[k] = sw[j];
            rk[k] = sR[j];
            sg[k] = sS[j];
        }
        float bias = b2[code];
        for (int i = 0; i <= NH; i++) {
            float A = 0.0f, Bv = 0.0f;
            #pragma unroll
            for (int k = 0; k < 4; k++) {
                bool act = (sg[k] > 0) ? (rk[k] < i) : (rk[k] >= i);
                if (act) {
                    A  = fmaf(v[k], vb[k], A);
                    Bv = fmaf(v[k], vw[k], Bv);
                }
            }
            #pragma unroll
            for (int off = 16; off >= 1; off >>= 1) {
                A  += __shfl_down_sync(FULLM, A,  off);
                Bv += __shfl_down_sync(FULLM, Bv, off);
            }
            if (lane == 0) {
                g_A[i * NCODES + code] = A + bias;
                g_B[i * NCODES + code] = Bv;
            }
        }
    } else if (blk == 32) {
        __shared__ float skv[NH];
        if (t < NH) {
            float w = w1[t], b = b1[t];
            skv[t] = (w != 0.0f) ? (-b / w) : pos_inf();
        }
        __syncthreads();
        if (t < NH) {
            float kv = skv[t];
            int r = 0;
            #pragma unroll 8
            for (int k = 0; k < NH; k++) {
                float o = skv[k];
                r += (o < kv) || (o == kv && k < t);
            }
            g_ksort[r] = kv;
            if (kv >= XMIN - 2.0f * CW && kv < XMAX + 2.0f * CW) {
                int g = (int)floorf((kv - XMIN) * INV_CW);
                #pragma unroll
                for (int d = -1; d <= 1; d++) {
                    int c = g + d;
                    if (c >= 0 && c < NCELLS) g_kinkNear[c] = 1;
                }
            }
        }
        if (t == 0) g_decb = dec_b[0];
    } else {
        // ---- score[c] = dec_w . emb[c]; 32 blocks x 16 warps = 512 warps ----
        int code = (blk - 33) * 16 + (t >> 5);
        const float* er = emb + code * 256;
        float s = 0.0f;
        #pragma unroll
        for (int k = 0; k < 8; k++) {
            int d = lane + (k << 5);
            s = fmaf(dec_w[d], er[d], s);
        }
        #pragma unroll
        for (int off = 16; off >= 1; off >>= 1)
            s += __shfl_down_sync(FULLM, s, off);
        if (lane == 0) g_score[code] = s;
    }
}

__device__ __forceinline__ int find_interval(const float* sk, float x) {
    int lo = 0, hi = NH;
    #pragma unroll
    for (int it = 0; it < 8; it++) {
        if (lo < hi) {
            int mid = (lo + hi) >> 1;
            if (sk[mid] <= x) lo = mid + 1; else hi = mid;
        }
    }
    return lo;   // number of kinks <= x, in [0,128]
}

// exact 512-line argmax from GLOBAL tables (rare fallback path in k_main)
__device__ __forceinline__ void scan512(const float* __restrict__ Ar,
                                        const float* __restrict__ Br,
                                        float xv, int lane, int& out_idx)
{
    float best = neg_inf(); int bi = 0;
    #pragma unroll
    for (int k = 0; k < 16; k++) {
        int c = lane + (k << 5);
        float v = fmaf(Br[c], xv, Ar[c]);
        if (v > best) { best = v; bi = c; }        // ascending c -> first-max per lane
    }
    #pragma unroll
    for (int off = 16; off >= 1; off >>= 1) {
        float ov = __shfl_down_sync(FULLM, best, off);
        int   oi = __shfl_down_sync(FULLM, bi,  off);
        if (ov > best || (ov == best && oi < bi)) { best = ov; bi = oi; }
    }
    out_idx = __shfl_sync(FULLM, bi, 0);           // jnp.argmax first-index semantics
}

// ======== kernel 2: coarse-to-fine classification with bisection, 1 coarse/warp ====
// Pairwise-dominance: within a kink-free span each line's dominance region is an
// interval -> equal endpoint argmax (+ same kink-interval) => constant throughout.
__global__ void k_classify()
{
    __shared__ float sk[NH];
    int tid = threadIdx.x;
    if (tid < NH) sk[tid] = g_ksort[tid];
    __syncthreads();
    int wg = blockIdx.x * (blockDim.x >> 5) + (tid >> 5);
    if (wg >= NCOARSE) return;
    int lane = tid & 31;

    float a[16], b[16];
    int iload = -1;
    int ivCur = 0;

    auto evalEdge = [&](int e) -> int {          // warp-cooperative 512-line argmax
        float x = XMIN + (float)e * CW;
        int iv = find_interval(sk, x);           // warp-uniform
        if (iv != iload) {
            const float* Ar = g_A + iv * NCODES + lane;
            const float* Br = g_B + iv * NCODES + lane;
            #pragma unroll
            for (int k = 0; k < 16; k++) { a[k] = Ar[k << 5]; b[k] = Br[k << 5]; }
            iload = iv;
        }
        ivCur = iv;
        float best = neg_inf(); int bi = 0;
        #pragma unroll
        for (int k = 0; k < 16; k++) {
            float v = fmaf(b[k], x, a[k]);
            if (v > best) { best = v; bi = lane + (k << 5); }
        }
        #pragma unroll
        for (int off = 16; off >= 1; off >>= 1) {
            float ov = __shfl_down_sync(FULLM, best, off);
            int   oi = __shfl_down_sync(FULLM, bi,  off);
            if (ov > best || (ov == best && oi < bi)) { best = ov; bi = oi; }
        }
        return __shfl_sync(FULLM, bi, 0);
    };

    auto fill = [&](int loE, int hiE, int arg) { // lanes cover <=16 cells in parallel
        int cell = loE + lane;
        if (cell < hiE)
            g_cellEnc[cell] =
                (unsigned short)(arg | (g_kinkNear[cell] ? 0x8000 : 0));
    };

    int loE = wg * 16, hiE = loE + 16;
    int argL = evalEdge(loE); int ivL = ivCur;
    int argR = evalEdge(hiE); int ivR = ivCur;
    if (argL == argR && ivL == ivR) {
        fill(loE, hiE, argL);
        return;
    }
    // warp-uniform bisection stack (depth <= 4)
    int sLo[8], sHi[8], sAL[8], sAH[8], sIL[8], sIH[8];
    sLo[0] = loE; sHi[0] = hiE; sAL[0] = argL; sAH[0] = argR;
    sIL[0] = ivL; sIH[0] = ivR;
    int sp = 1;
    while (sp) {
        sp--;
        int lo = sLo[sp], hi = sHi[sp];
        int aL = sAL[sp], aH = sAH[sp], iL = sIL[sp], iH = sIH[sp];
        if (aL == aH && iL == iH) { fill(lo, hi, aL); continue; }
        if (hi - lo == 1) {                      // boundary/kink inside: bad cell
            if (lane == 0)
                g_cellEnc[lo] = (unsigned short)(aL | 0x8000);
            continue;
        }
        int mid = (lo + hi) >> 1;
        int aM = evalEdge(mid);
        int iM = ivCur;
        sLo[sp] = lo;  sHi[sp] = mid; sAL[sp] = aL; sAH[sp] = aM;
        sIL[sp] = iL;  sIH[sp] = iM;  sp++;
        sLo[sp] = mid; sHi[sp] = hi;  sAL[sp] = aM; sAH[sp] = aH;
        sIL[sp] = iM;  sIH[sp] = iH;  sp++;
    }
}

// ======== kernel 3: 2 elems/thread, u16 gather + smem score LUT + rare fallback ====
__global__ void k_main(const float* __restrict__ x_in, float* __restrict__ out,
                       int n, int write_idx)
{
    __shared__ float s_sc[NCODES];
    __shared__ float s_sk[NH];
    int tid = threadIdx.x;
    s_sc[tid] = g_score[tid];
    s_sc[tid + 256] = g_score[tid + 256];
    if (tid < NH) s_sk[tid] = g_ksort[tid];
    __syncthreads();
    float db = g_decb;

    int base = (blockIdx.x * blockDim.x + tid) * 2;
    bool a0 = base < n, a1 = base + 1 < n;
    float x0 = 0.0f, x1 = 0.0f;
    if (a1) { float2 xv = *(const float2*)(x_in + base); x0 = xv.x; x1 = xv.y; }
    else if (a0) x0 = x_in[base];

    int idx0 = 0, idx1 = 0;
    bool need0 = a0, need1 = a1;
    unsigned enc0 = 0, enc1 = 0;
    if (a0 && x0 >= XMIN && x0 < XMAX) {
        int g = (int)((x0 - XMIN) * INV_CW);
        if (g >= NCELLS) g = NCELLS - 1;
        enc0 = g_cellEnc[g];
        need0 = (enc0 & 0x8000u) != 0;
    }
    if (a1 && x1 >= XMIN && x1 < XMAX) {
        int g = (int)((x1 - XMIN) * INV_CW);
        if (g >= NCELLS) g = NCELLS - 1;
        enc1 = g_cellEnc[g];
        need1 = (enc1 & 0x8000u) != 0;
    }
    idx0 = enc0 & 511;
    idx1 = enc1 & 511;

    int lane = tid & 31;
    unsigned m = __ballot_sync(FULLM, need0);
    while (m) {
        int src = __ffs(m) - 1; m &= m - 1;
        float xb = __shfl_sync(FULLM, x0, src);
        int ib = find_interval(s_sk, xb);        // warp-uniform
        int bi;
        scan512(g_A + ib * NCODES, g_B + ib * NCODES, xb, lane, bi);
        if (lane == src) idx0 = bi;
    }
    m = __ballot_sync(FULLM, need1);
    while (m) {
        int src = __ffs(m) - 1; m &= m - 1;
        float xb = __shfl_sync(FULLM, x1, src);
        int ib = find_interval(s_sk, xb);
        int bi;
        scan512(g_A + ib * NCODES, g_B + ib * NCODES, xb, lane, bi);
        if (lane == src) idx1 = bi;
    }

    if (a1) {
        *(float2*)(out + base) = make_float2(s_sc[idx0] + db, s_sc[idx1] + db);
        if (write_idx)
            *(float2*)(out + n + base) = make_float2((float)idx0, (float)idx1);
    } else if (a0) {
        out[base] = s_sc[idx0] + db;
        if (write_idx) out[n + base] = (float)idx0;
    }
}

extern "C" void kernel_launch(void* const* d_in, const int* in_sizes, int n_in,
                              void* d_out, int out_size)
{
    const float* x     = (const float*)d_in[0];
    const float* w1    = (const float*)d_in[1];
    const float* b1    = (const float*)d_in[2];
    const float* w2    = (const float*)d_in[3];
    const float* b2    = (const float*)d_in[4];
    const float* emb   = (const float*)d_in[5];
    const float* dec_w = (const float*)d_in[6];
    const float* dec_b = (const float*)d_in[7];
    int n = in_sizes[0];
    float* out = (float*)d_out;

    k_prep<<<65, 512>>>(w1, b1, w2, b2, emb, dec_w, dec_b);
    k_classify<<<NCOARSE / 8, 256>>>();
    int write_idx = (out_size >= 2 * n) ? 1 : 0;
    int nth = (n + 1) / 2;
    k_main<<<(nth + 255) / 256, 256>>>(x, out, n, write_idx);
}

// round 13
// speedup vs baseline: 2.1122x; 2.1122x over previous
#include <cuda_runtime.h>
#include <cstdint>

#define NH      128
#define NCODES  512
#define NCELLS  65536
#define NCOARSE 4096                   // 16 fine cells per coarse cell
#define XMIN    (-5.75f)
#define XMAX    (5.75f)
#define CW      (11.5f / 65536.0f)
#define INV_CW  (65536.0f / 11.5f)
#define FULLM   0xffffffffu

__device__ __forceinline__ float neg_inf() { return __int_as_float(0xff800000); }
__device__ __forceinline__ float pos_inf() { return __int_as_float(0x7f800000); }

// -------- device scratch (no allocation allowed) --------
__device__ float    g_ksort[NH];        // sorted kink positions (+inf padded)
__device__ float    g_A[129 * NCODES];  // per-interval intercepts
__device__ float    g_B[129 * NCODES];  // per-interval slopes
__device__ float    g_score[NCODES];    // dec_w . emb[c]
__device__ float    g_decb;
__device__ unsigned char g_kinkNear[NCELLS];   // set-only, deterministic per replay
__device__ unsigned short g_cellEnc[NCELLS];   // idx | (bad ? 0x8000 : 0)

// ======== kernel 1 (fused prep) ========
// blocks 0..128  : A/B for interval i = blk; thread = code; w2 staged via smem
// block  129     : sorted kinks + kink-adjacent cell flags + decoder bias
// blocks 130..161: score[c] = dec_w . emb[c]
__global__ void k_prep(const float* __restrict__ w1, const float* __restrict__ b1,
                       const float* __restrict__ w2, const float* __restrict__ b2,
                       const float* __restrict__ emb, const float* __restrict__ dec_w,
                       const float* __restrict__ dec_b)
{
    int blk = blockIdx.x;
    int t = threadIdx.x;                 // 512 threads
    if (blk < 129) {
        __shared__ float sw[NH], sb[NH], skv[NH];
        __shared__ int   sR[NH], sS[NH];
        __shared__ float s2[NCODES * 17];          // 16 j-cols, padded to 17
        if (t < NH) {
            float w = w1[t], b = b1[t];
            sw[t] = w; sb[t] = b;
            skv[t] = (w != 0.0f) ? (-b / w) : pos_inf();
        }
        __syncthreads();
        if (t < NH) {
            float kv = skv[t];
            int r = 0;
            #pragma unroll 8
            for (int k = 0; k < NH; k++) {
                float o = skv[k];
                r += (o < kv) || (o == kv && k < t);   // unique rank, index tiebreak
            }
            float w = sw[t], b = sb[t];
            sR[t] = (w != 0.0f) ? r : NH;
            sS[t] = (w > 0.0f) ? 1 : ((w < 0.0f) ? -1 : ((b > 0.0f) ? -1 : 1));
        }
        __syncthreads();
        int i = blk;                     // interval 0..128
        float A = b2[t], Bv = 0.0f;      // j-ascending order == previous direct sums
        for (int ch = 0; ch < 8; ch++) {
            // coalesced stage of w2[:, ch*16 .. ch*16+15] into padded smem
            #pragma unroll
            for (int r = 0; r < 16; r++) {
                int idx = t + (r << 9);              // [0, 8192)
                int c = idx >> 4, jj = idx & 15;
                s2[c * 17 + jj] = w2[c * NH + (ch << 4) + jj];
            }
            __syncthreads();
            #pragma unroll
            for (int jj = 0; jj < 16; jj++) {
                int j = (ch << 4) + jj;
                bool act = (sS[j] > 0) ? (sR[j] < i) : (sR[j] >= i);
                if (act) {
                    float v = s2[t * 17 + jj];       // stride 17: conflict-free
                    A  = fmaf(v, sb[j], A);
                    Bv = fmaf(v, sw[j], Bv);
                }
            }
            __syncthreads();                         // before next chunk overwrite
        }
        g_A[i * NCODES + t] = A;
        g_B[i * NCODES + t] = Bv;
    } else if (blk == 129) {
        __shared__ float skv[NH];
        if (t < NH) {
            float w = w1[t], b = b1[t];
            skv[t] = (w != 0.0f) ? (-b / w) : pos_inf();
        }
        __syncthreads();
        if (t < NH) {
            float kv = skv[t];
            int r = 0;
            #pragma unroll 8
            for (int k = 0; k < NH; k++) {
                float o = skv[k];
                r += (o < kv) || (o == kv && k < t);
            }
            g_ksort[r] = kv;
            if (kv >= XMIN - 2.0f * CW && kv < XMAX + 2.0f * CW) {
                int g = (int)floorf((kv - XMIN) * INV_CW);
                #pragma unroll
                for (int d = -1; d <= 1; d++) {
                    int c = g + d;
                    if (c >= 0 && c < NCELLS) g_kinkNear[c] = 1;
                }
            }
        }
        if (t == 0) g_decb = dec_b[0];
    } else {
        // ---- score[c] = dec_w . emb[c]; 32 blocks x 16 warps = 512 warps ----
        int code = (blk - 130) * 16 + (t >> 5);
        int lane = t & 31;
        const float* er = emb + code * 256;
        float s = 0.0f;
        #pragma unroll
        for (int k = 0; k < 8; k++) {
            int d = lane + (k << 5);
            s = fmaf(dec_w[d], er[d], s);
        }
        #pragma unroll
        for (int off = 16; off >= 1; off >>= 1)
            s += __shfl_down_sync(FULLM, s, off);
        if (lane == 0) g_score[code] = s;
    }
}

__device__ __forceinline__ int find_interval(const float* sk, float x) {
    int lo = 0, hi = NH;
    #pragma unroll
    for (int it = 0; it < 8; it++) {
        if (lo < hi) {
            int mid = (lo + hi) >> 1;
            if (sk[mid] <= x) lo = mid + 1; else hi = mid;
        }
    }
    return lo;   // number of kinks <= x, in [0,128]
}

// exact 512-line argmax from GLOBAL tables (rare fallback path in k_main)
__device__ __forceinline__ void scan512(const float* __restrict__ Ar,
                                        const float* __restrict__ Br,
                                        float xv, int lane, int& out_idx)
{
    float best = neg_inf(); int bi = 0;
    #pragma unroll
    for (int k = 0; k < 16; k++) {
        int c = lane + (k << 5);
        float v = fmaf(Br[c], xv, Ar[c]);
        if (v > best) { best = v; bi = c; }        // ascending c -> first-max per lane
    }
    #pragma unroll
    for (int off = 16; off >= 1; off >>= 1) {
        float ov = __shfl_down_sync(FULLM, best, off);
        int   oi = __shfl_down_sync(FULLM, bi,  off);
        if (ov > best || (ov == best && oi < bi)) { best = ov; bi = oi; }
    }
    out_idx = __shfl_sync(FULLM, bi, 0);           // jnp.argmax first-index semantics
}

// ======== kernel 2: coarse-to-fine classification with bisection, 1 coarse/warp ====
// Pairwise-dominance: within a kink-free span each line's dominance region is an
// interval -> equal endpoint argmax (+ same kink-interval) => constant throughout.
__global__ void k_classify()
{
    __shared__ float sk[NH];
    int tid = threadIdx.x;
    if (tid < NH) sk[tid] = g_ksort[tid];
    __syncthreads();
    int wg = blockIdx.x * (blockDim.x >> 5) + (tid >> 5);
    if (wg >= NCOARSE) return;
    int lane = tid & 31;

    float a[16], b[16];
    int iload = -1;
    int ivCur = 0;

    auto evalEdge = [&](int e) -> int {          // warp-cooperative 512-line argmax
        float x = XMIN + (float)e * CW;
        int iv = find_interval(sk, x);           // warp-uniform
        if (iv != iload) {
            const float* Ar = g_A + iv * NCODES + lane;
            const float* Br = g_B + iv * NCODES + lane;
            #pragma unroll
            for (int k = 0; k < 16; k++) { a[k] = Ar[k << 5]; b[k] = Br[k << 5]; }
            iload = iv;
        }
        ivCur = iv;
        float best = neg_inf(); int bi = 0;
        #pragma unroll
        for (int k = 0; k < 16; k++) {
            float v = fmaf(b[k], x, a[k]);
            if (v > best) { best = v; bi = lane + (k << 5); }
        }
        #pragma unroll
        for (int off = 16; off >= 1; off >>= 1) {
            float ov = __shfl_down_sync(FULLM, best, off);
            int   oi = __shfl_down_sync(FULLM, bi,  off);
            if (ov > best || (ov == best && oi < bi)) { best = ov; bi = oi; }
        }
        return __shfl_sync(FULLM, bi, 0);
    };

    auto fill = [&](int loE, int hiE, int arg) { // lanes cover <=16 cells in parallel
        int cell = loE + lane;
        if (cell < hiE)
            g_cellEnc[cell] =
                (unsigned short)(arg | (g_kinkNear[cell] ? 0x8000 : 0));
    };

    int loE = wg * 16, hiE = loE + 16;
    int argL = evalEdge(loE); int ivL = ivCur;
    int argR = evalEdge(hiE); int ivR = ivCur;
    if (argL == argR && ivL == ivR) {
        fill(loE, hiE, argL);
        return;
    }
    // warp-uniform bisection stack (depth <= 4)
    int sLo[8], sHi[8], sAL[8], sAH[8], sIL[8], sIH[8];
    sLo[0] = loE; sHi[0] = hiE; sAL[0] = argL; sAH[0] = argR;
    sIL[0] = ivL; sIH[0] = ivR;
    int sp = 1;
    while (sp) {
        sp--;
        int lo = sLo[sp], hi = sHi[sp];
        int aL = sAL[sp], aH = sAH[sp], iL = sIL[sp], iH = sIH[sp];
        if (aL == aH && iL == iH) { fill(lo, hi, aL); continue; }
        if (hi - lo == 1) {                      // boundary/kink inside: bad cell
            if (lane == 0)
                g_cellEnc[lo] = (unsigned short)(aL | 0x8000);
            continue;
        }
        int mid = (lo + hi) >> 1;
        int aM = evalEdge(mid);
        int iM = ivCur;
        sLo[sp] = lo;  sHi[sp] = mid; sAL[sp] = aL; sAH[sp] = aM;
        sIL[sp] = iL;  sIH[sp] = iM;  sp++;
        sLo[sp] = mid; sHi[sp] = hi;  sAL[sp] = aM; sAH[sp] = aH;
        sIL[sp] = iM;  sIH[sp] = iH;  sp++;
    }
}

// ======== kernel 3: 2 elems/thread, u16 gather + smem score LUT + rare fallback ====
__global__ void k_main(const float* __restrict__ x_in, float* __restrict__ out,
                       int n, int write_idx)
{
    __shared__ float s_sc[NCODES];
    __shared__ float s_sk[NH];
    int tid = threadIdx.x;
    s_sc[tid] = g_score[tid];
    s_sc[tid + 256] = g_score[tid + 256];
    if (tid < NH) s_sk[tid] = g_ksort[tid];
    __syncthreads();
    float db = g_decb;

    int base = (blockIdx.x * blockDim.x + tid) * 2;
    bool a0 = base < n, a1 = base + 1 < n;
    float x0 = 0.0f, x1 = 0.0f;
    if (a1) { float2 xv = *(const float2*)(x_in + base); x0 = xv.x; x1 = xv.y; }
    else if (a0) x0 = x_in[base];

    int idx0 = 0, idx1 = 0;
    bool need0 = a0, need1 = a1;
    unsigned enc0 = 0, enc1 = 0;
    if (a0 && x0 >= XMIN && x0 < XMAX) {
        int g = (int)((x0 - XMIN) * INV_CW);
        if (g >= NCELLS) g = NCELLS - 1;
        enc0 = g_cellEnc[g];
        need0 = (enc0 & 0x8000u) != 0;
    }
    if (a1 && x1 >= XMIN && x1 < XMAX) {
        int g = (int)((x1 - XMIN) * INV_CW);
        if (g >= NCELLS) g = NCELLS - 1;
        enc1 = g_cellEnc[g];
        need1 = (enc1 & 0x8000u) != 0;
    }
    idx0 = enc0 & 511;
    idx1 = enc1 & 511;

    int lane = tid & 31;
    unsigned m = __ballot_sync(FULLM, need0);
    while (m) {
        int src = __ffs(m) - 1; m &= m - 1;
        float xb = __shfl_sync(FULLM, x0, src);
        int ib = find_interval(s_sk, xb);        // warp-uniform
        int bi;
        scan512(g_A + ib * NCODES, g_B + ib * NCODES, xb, lane, bi);
        if (lane == src) idx0 = bi;
    }
    m = __ballot_sync(FULLM, need1);
    while (m) {
        int src = __ffs(m) - 1; m &= m - 1;
        float xb = __shfl_sync(FULLM, x1, src);
        int ib = find_interval(s_sk, xb);
        int bi;
        scan512(g_A + ib * NCODES, g_B + ib * NCODES, xb, lane, bi);
        if (lane == src) idx1 = bi;
    }

    if (a1) {
        *(float2*)(out + base) = make_float2(s_sc[idx0] + db, s_sc[idx1] + db);
        if (write_idx)
            *(float2*)(out + n + base) = make_float2((float)idx0, (float)idx1);
    } else if (a0) {
        out[base] = s_sc[idx0] + db;
        if (write_idx) out[n + base] = (float)idx0;
    }
}

extern "C" void kernel_launch(void* const* d_in, const int* in_sizes, int n_in,
                              void* d_out, int out_size)
{
    const float* x     = (const float*)d_in[0];
    const float* w1    = (const float*)d_in[1];
    const float* b1    = (const float*)d_in[2];
    const float* w2    = (const float*)d_in[3];
    const float* b2    = (const float*)d_in[4];
    const float* emb   = (const float*)d_in[5];
    const float* dec_w = (const float*)d_in[6];
    const float* dec_b = (const float*)d_in[7];
    int n = in_sizes[0];
    float* out = (float*)d_out;

    k_prep<<<162, 512>>>(w1, b1, w2, b2, emb, dec_w, dec_b);
    k_classify<<<NCOARSE / 8, 256>>>();
    int write_idx = (out_size >= 2 * n) ? 1 : 0;
    int nth = (n + 1) / 2;
    k_main<<<(nth + 255) / 256, 256>>>(x, out, n, write_idx);
}

// round 14
// speedup vs baseline: 2.4846x; 1.1763x over previous
#include <cuda_runtime.h>
#include <cstdint>

#define NH      128
#define NCODES  512
#define NCELLS  65536
#define NCOARSE 4096                   // 16 fine cells per coarse cell
#define XMIN    (-5.75f)
#define XMAX    (5.75f)
#define CW      (11.5f / 65536.0f)
#define INV_CW  (65536.0f / 11.5f)
#define FULLM   0xffffffffu

__device__ __forceinline__ float neg_inf() { return __int_as_float(0xff800000); }
__device__ __forceinline__ float pos_inf() { return __int_as_float(0x7f800000); }

// -------- device scratch (no allocation allowed) --------
__device__ float    g_ksort[NH];        // sorted kink positions (+inf padded)
__device__ int      g_actRank[NH];      // rank for activity test (128 = never)
__device__ int      g_sgn[NH];
__device__ float    g_w2t[NH * NCODES]; // transposed w2: [j][code]
__device__ float    g_A[129 * NCODES];  // per-interval intercepts
__device__ float    g_B[129 * NCODES];  // per-interval slopes
__device__ float    g_score[NCODES];    // dec_w . emb[c]
__device__ float    g_decb;
__device__ unsigned char g_kinkNear[NCELLS];   // set-only, deterministic per replay
__device__ unsigned short g_cellEnc[NCELLS];   // idx | (bad ? 0x8000 : 0)

// ======== kernel 1 (k_pre): blocks 0..63 transpose w2, block 64 ranks/kinks,
//          blocks 65..128 scores ========
__global__ void k_pre(const float* __restrict__ w1, const float* __restrict__ b1,
                      const float* __restrict__ w2, const float* __restrict__ emb,
                      const float* __restrict__ dec_w, const float* __restrict__ dec_b)
{
    int blk = blockIdx.x;
    int t = threadIdx.x;                 // 256 threads
    if (blk < 64) {
        // ---- 32x32 tile transpose: w2[512][128] -> w2t[128][512] ----
        __shared__ float tl[32][33];
        int tj = blk & 3, tc = blk >> 2;           // j-tile 0..3, c-tile 0..15
        int tx = t & 31, ty = t >> 5;              // 8 rows per pass
        #pragma unroll
        for (int r = 0; r < 4; r++) {
            int row = ty + r * 8;                  // c within tile
            tl[row][tx] = w2[(tc * 32 + row) * NH + tj * 32 + tx];   // coalesced
        }
        __syncthreads();
        #pragma unroll
        for (int r = 0; r < 4; r++) {
            int row = ty + r * 8;                  // j within tile
            g_w2t[(tj * 32 + row) * NCODES + tc * 32 + tx] = tl[tx][row]; // coalesced
        }
    } else if (blk == 64) {
        // ---- sorted kinks + ranks/signs + kink-adjacent flags + decoder bias ----
        __shared__ float skv[NH];
        if (t < NH) {
            float w = w1[t], b = b1[t];
            skv[t] = (w != 0.0f) ? (-b / w) : pos_inf();
        }
        __syncthreads();
        if (t < NH) {
            float kv = skv[t];
            int r = 0;
            #pragma unroll 8
            for (int k = 0; k < NH; k++) {
                float o = skv[k];
                r += (o < kv) || (o == kv && k < t);   // unique rank, index tiebreak
            }
            g_ksort[r] = kv;
            float w = w1[t], b = b1[t];
            g_actRank[t] = (w != 0.0f) ? r : NH;
            g_sgn[t] = (w > 0.0f) ? 1 : ((w < 0.0f) ? -1 : ((b > 0.0f) ? -1 : 1));
            if (kv >= XMIN - 2.0f * CW && kv < XMAX + 2.0f * CW) {
                int g = (int)floorf((kv - XMIN) * INV_CW);
                #pragma unroll
                for (int d = -1; d <= 1; d++) {
                    int c = g + d;
                    if (c >= 0 && c < NCELLS) g_kinkNear[c] = 1;
                }
            }
        }
        if (t == 0) g_decb = dec_b[0];
    } else {
        // ---- score[c] = dec_w . emb[c]; 64 blocks x 8 warps = 512 warps ----
        int code = (blk - 65) * 8 + (t >> 5);
        int lane = t & 31;
        const float* er = emb + code * 256;
        float s = 0.0f;
        #pragma unroll
        for (int k = 0; k < 8; k++) {
            int d = lane + (k << 5);
            s = fmaf(dec_w[d], er[d], s);
        }
        #pragma unroll
        for (int off = 16; off >= 1; off >>= 1)
            s += __shfl_down_sync(FULLM, s, off);
        if (lane == 0) g_score[code] = s;
    }
}

// ======== kernel 2 (k_ab): block = interval, thread = code, coalesced w2t stream ====
// Activity folded into pre-zeroed multipliers: fmaf(v,0,A)==A exactly, so the
// j-ascending direct sum is bit-identical to the previous kernels' tables.
__global__ void k_ab(const float* __restrict__ w1, const float* __restrict__ b1,
                     const float* __restrict__ b2)
{
    __shared__ float sbm[NH], swm[NH];
    int t = threadIdx.x;                 // 512 threads = code
    int i = blockIdx.x;                  // interval 0..128
    if (t < NH) {
        int r = g_actRank[t], s = g_sgn[t];
        bool act = (s > 0) ? (r < i) : (r >= i);
        sbm[t] = act ? b1[t] : 0.0f;
        swm[t] = act ? w1[t] : 0.0f;
    }
    __syncthreads();
    float A = b2[t], Bv = 0.0f;
    const float* wt = g_w2t + t;
    #pragma unroll 8
    for (int j = 0; j < NH; j++) {
        float v = wt[j * NCODES];        // coalesced: one 128B line per warp-LDG
        A  = fmaf(v, sbm[j], A);         // smem broadcast reads, conflict-free
        Bv = fmaf(v, swm[j], Bv);
    }
    g_A[i * NCODES + t] = A;
    g_B[i * NCODES + t] = Bv;
}

__device__ __forceinline__ int find_interval(const float* sk, float x) {
    int lo = 0, hi = NH;
    #pragma unroll
    for (int it = 0; it < 8; it++) {
        if (lo < hi) {
            int mid = (lo + hi) >> 1;
            if (sk[mid] <= x) lo = mid + 1; else hi = mid;
        }
    }
    return lo;   // number of kinks <= x, in [0,128]
}

// exact 512-line argmax from GLOBAL tables (rare fallback path in k_main)
__device__ __forceinline__ void scan512(const float* __restrict__ Ar,
                                        const float* __restrict__ Br,
                                        float xv, int lane, int& out_idx)
{
    float best = neg_inf(); int bi = 0;
    #pragma unroll
    for (int k = 0; k < 16; k++) {
        int c = lane + (k << 5);
        float v = fmaf(Br[c], xv, Ar[c]);
        if (v > best) { best = v; bi = c; }        // ascending c -> first-max per lane
    }
    #pragma unroll
    for (int off = 16; off >= 1; off >>= 1) {
        float ov = __shfl_down_sync(FULLM, best, off);
        int   oi = __shfl_down_sync(FULLM, bi,  off);
        if (ov > best || (ov == best && oi < bi)) { best = ov; bi = oi; }
    }
    out_idx = __shfl_sync(FULLM, bi, 0);           // jnp.argmax first-index semantics
}

// ======== kernel 3: coarse-to-fine classification with bisection, 1 coarse/warp ====
// Pairwise-dominance: within a kink-free span each line's dominance region is an
// interval -> equal endpoint argmax (+ same kink-interval) => constant throughout.
__global__ void k_classify()
{
    __shared__ float sk[NH];
    int tid = threadIdx.x;
    if (tid < NH) sk[tid] = g_ksort[tid];
    __syncthreads();
    int wg = blockIdx.x * (blockDim.x >> 5) + (tid >> 5);
    if (wg >= NCOARSE) return;
    int lane = tid & 31;

    float a[16], b[16];
    int iload = -1;
    int ivCur = 0;

    auto evalEdge = [&](int e) -> int {          // warp-cooperative 512-line argmax
        float x = XMIN + (float)e * CW;
        int iv = find_interval(sk, x);           // warp-uniform
        if (iv != iload) {
            const float* Ar = g_A + iv * NCODES + lane;
            const float* Br = g_B + iv * NCODES + lane;
            #pragma unroll
            for (int k = 0; k < 16; k++) { a[k] = Ar[k << 5]; b[k] = Br[k << 5]; }
            iload = iv;
        }
        ivCur = iv;
        float best = neg_inf(); int bi = 0;
        #pragma unroll
        for (int k = 0; k < 16; k++) {
            float v = fmaf(b[k], x, a[k]);
            if (v > best) { best = v; bi = lane + (k << 5); }
        }
        #pragma unroll
        for (int off = 16; off >= 1; off >>= 1) {
            float ov = __shfl_down_sync(FULLM, best, off);
            int   oi = __shfl_down_sync(FULLM, bi,  off);
            if (ov > best || (ov == best && oi < bi)) { best = ov; bi = oi; }
        }
        return __shfl_sync(FULLM, bi, 0);
    };

    auto fill = [&](int loE, int hiE, int arg) { // lanes cover <=16 cells in parallel
        int cell = loE + lane;
        if (cell < hiE)
            g_cellEnc[cell] =
                (unsigned short)(arg | (g_kinkNear[cell] ? 0x8000 : 0));
    };

    int loE = wg * 16, hiE = loE + 16;
    int argL = evalEdge(loE); int ivL = ivCur;
    int argR = evalEdge(hiE); int ivR = ivCur;
    if (argL == argR && ivL == ivR) {
        fill(loE, hiE, argL);
        return;
    }
    // warp-uniform bisection stack (depth <= 4)
    int sLo[8], sHi[8], sAL[8], sAH[8], sIL[8], sIH[8];
    sLo[0] = loE; sHi[0] = hiE; sAL[0] = argL; sAH[0] = argR;
    sIL[0] = ivL; sIH[0] = ivR;
    int sp = 1;
    while (sp) {
        sp--;
        int lo = sLo[sp], hi = sHi[sp];
        int aL = sAL[sp], aH = sAH[sp], iL = sIL[sp], iH = sIH[sp];
        if (aL == aH && iL == iH) { fill(lo, hi, aL); continue; }
        if (hi - lo == 1) {                      // boundary/kink inside: bad cell
            if (lane == 0)
                g_cellEnc[lo] = (unsigned short)(aL | 0x8000);
            continue;
        }
        int mid = (lo + hi) >> 1;
        int aM = evalEdge(mid);
        int iM = ivCur;
        sLo[sp] = lo;  sHi[sp] = mid; sAL[sp] = aL; sAH[sp] = aM;
        sIL[sp] = iL;  sIH[sp] = iM;  sp++;
        sLo[sp] = mid; sHi[sp] = hi;  sAL[sp] = aM; sAH[sp] = aH;
        sIL[sp] = iM;  sIH[sp] = iH;  sp++;
    }
}

// ======== kernel 4: 2 elems/thread, u16 gather + smem score LUT + rare fallback ====
__global__ void k_main(const float* __restrict__ x_in, float* __restrict__ out,
                       int n, int write_idx)
{
    __shared__ float s_sc[NCODES];
    __shared__ float s_sk[NH];
    int tid = threadIdx.x;
    s_sc[tid] = g_score[tid];
    s_sc[tid + 256] = g_score[tid + 256];
    if (tid < NH) s_sk[tid] = g_ksort[tid];
    __syncthreads();
    float db = g_decb;

    int base = (blockIdx.x * blockDim.x + tid) * 2;
    bool a0 = base < n, a1 = base + 1 < n;
    float x0 = 0.0f, x1 = 0.0f;
    if (a1) { float2 xv = *(const float2*)(x_in + base); x0 = xv.x; x1 = xv.y; }
    else if (a0) x0 = x_in[base];

    int idx0 = 0, idx1 = 0;
    bool need0 = a0, need1 = a1;
    unsigned enc0 = 0, enc1 = 0;
    if (a0 && x0 >= XMIN && x0 < XMAX) {
        int g = (int)((x0 - XMIN) * INV_CW);
        if (g >= NCELLS) g = NCELLS - 1;
        enc0 = g_cellEnc[g];
        need0 = (enc0 & 0x8000u) != 0;
    }
    if (a1 && x1 >= XMIN && x1 < XMAX) {
        int g = (int)((x1 - XMIN) * INV_CW);
        if (g >= NCELLS) g = NCELLS - 1;
        enc1 = g_cellEnc[g];
        need1 = (enc1 & 0x8000u) != 0;
    }
    idx0 = enc0 & 511;
    idx1 = enc1 & 511;

    int lane = tid & 31;
    unsigned m = __ballot_sync(FULLM, need0);
    while (m) {
        int src = __ffs(m) - 1; m &= m - 1;
        float xb = __shfl_sync(FULLM, x0, src);
        int ib = find_interval(s_sk, xb);        // warp-uniform
        int bi;
        scan512(g_A + ib * NCODES, g_B + ib * NCODES, xb, lane, bi);
        if (lane == src) idx0 = bi;
    }
    m = __ballot_sync(FULLM, need1);
    while (m) {
        int src = __ffs(m) - 1; m &= m - 1;
        float xb = __shfl_sync(FULLM, x1, src);
        int ib = find_interval(s_sk, xb);
        int bi;
        scan512(g_A + ib * NCODES, g_B + ib * NCODES, xb, lane, bi);
        if (lane == src) idx1 = bi;
    }

    if (a1) {
        *(float2*)(out + base) = make_float2(s_sc[idx0] + db, s_sc[idx1] + db);
        if (write_idx)
            *(float2*)(out + n + base) = make_float2((float)idx0, (float)idx1);
    } else if (a0) {
        out[base] = s_sc[idx0] + db;
        if (write_idx) out[n + base] = (float)idx0;
    }
}

extern "C" void kernel_launch(void* const* d_in, const int* in_sizes, int n_in,
                              void* d_out, int out_size)
{
    const float* x     = (const float*)d_in[0];
    const float* w1    = (const float*)d_in[1];
    const float* b1    = (const float*)d_in[2];
    const float* w2    = (const float*)d_in[3];
    const float* b2    = (const float*)d_in[4];
    const float* emb   = (const float*)d_in[5];
    const float* dec_w = (const float*)d_in[6];
    const float* dec_b = (const float*)d_in[7];
    int n = in_sizes[0];
    float* out = (float*)d_out;

    k_pre<<<129, 256>>>(w1, b1, w2, emb, dec_w, dec_b);
    k_ab<<<129, 512>>>(w1, b1, b2);
    k_classify<<<NCOARSE / 8, 256>>>();
    int write_idx = (out_size >= 2 * n) ? 1 : 0;
    int nth = (n + 1) / 2;
    k_main<<<(nth + 255) / 256, 256>>>(x, out, n, write_idx);
}

// round 15
// speedup vs baseline: 2.6909x; 1.0830x over previous
#include <cuda_runtime.h>
#include <cstdint>

#define NH      128
#define NCODES  512
#define NCELLS  65536
#define NCOARSE 4096                   // 16 fine cells per coarse cell
#define XMIN    (-5.75f)
#define XMAX    (5.75f)
#define CW      (11.5f / 65536.0f)
#define INV_CW  (65536.0f / 11.5f)
#define FULLM   0xffffffffu

__device__ __forceinline__ float neg_inf() { return __int_as_float(0xff800000); }
__device__ __forceinline__ float pos_inf() { return __int_as_float(0x7f800000); }

// -------- device scratch (no allocation allowed) --------
__device__ float    g_ksort[NH];        // sorted kink positions (+inf padded)
__device__ int      g_actRank[NH];      // rank for activity test (128 = never)
__device__ int      g_sgn[NH];
__device__ float    g_w2t[NH * NCODES]; // transposed w2: [j][code]
__device__ float    g_A[129 * NCODES];  // per-interval intercepts
__device__ float    g_B[129 * NCODES];  // per-interval slopes
__device__ float    g_score[NCODES];    // dec_w . emb[c]
__device__ float    g_decb;
__device__ unsigned char g_kinkNear[NCELLS];   // set-only, deterministic per replay
__device__ unsigned short g_cellEnc[NCELLS];   // fine: idx | (bad ? 0x8000 : 0)
__device__ unsigned short g_coarseEnc[NCOARSE];// coarse: idx, or 0x8000 = consult fine

// ======== kernel 1 (k_pre): blocks 0..63 transpose w2, block 64 ranks/kinks,
//          blocks 65..128 scores ========
__global__ void k_pre(const float* __restrict__ w1, const float* __restrict__ b1,
                      const float* __restrict__ w2, const float* __restrict__ emb,
                      const float* __restrict__ dec_w, const float* __restrict__ dec_b)
{
    int blk = blockIdx.x;
    int t = threadIdx.x;                 // 256 threads
    if (blk < 64) {
        // ---- 32x32 tile transpose: w2[512][128] -> w2t[128][512] ----
        __shared__ float tl[32][33];
        int tj = blk & 3, tc = blk >> 2;           // j-tile 0..3, c-tile 0..15
        int tx = t & 31, ty = t >> 5;              // 8 rows per pass
        #pragma unroll
        for (int r = 0; r < 4; r++) {
            int row = ty + r * 8;                  // c within tile
            tl[row][tx] = w2[(tc * 32 + row) * NH + tj * 32 + tx];   // coalesced
        }
        __syncthreads();
        #pragma unroll
        for (int r = 0; r < 4; r++) {
            int row = ty + r * 8;                  // j within tile
            g_w2t[(tj * 32 + row) * NCODES + tc * 32 + tx] = tl[tx][row]; // coalesced
        }
    } else if (blk == 64) {
        // ---- sorted kinks + ranks/signs + kink-adjacent flags + decoder bias ----
        __shared__ float skv[NH];
        if (t < NH) {
            float w = w1[t], b = b1[t];
            skv[t] = (w != 0.0f) ? (-b / w) : pos_inf();
        }
        __syncthreads();
        if (t < NH) {
            float kv = skv[t];
            int r = 0;
            #pragma unroll 8
            for (int k = 0; k < NH; k++) {
                float o = skv[k];
                r += (o < kv) || (o == kv && k < t);   // unique rank, index tiebreak
            }
            g_ksort[r] = kv;
            float w = w1[t], b = b1[t];
            g_actRank[t] = (w != 0.0f) ? r : NH;
            g_sgn[t] = (w > 0.0f) ? 1 : ((w < 0.0f) ? -1 : ((b > 0.0f) ? -1 : 1));
            if (kv >= XMIN - 2.0f * CW && kv < XMAX + 2.0f * CW) {
                int g = (int)floorf((kv - XMIN) * INV_CW);
                #pragma unroll
                for (int d = -1; d <= 1; d++) {
                    int c = g + d;
                    if (c >= 0 && c < NCELLS) g_kinkNear[c] = 1;
                }
            }
        }
        if (t == 0) g_decb = dec_b[0];
    } else {
        // ---- score[c] = dec_w . emb[c]; 64 blocks x 8 warps = 512 warps ----
        int code = (blk - 65) * 8 + (t >> 5);
        int lane = t & 31;
        const float* er = emb + code * 256;
        float s = 0.0f;
        #pragma unroll
        for (int k = 0; k < 8; k++) {
            int d = lane + (k << 5);
            s = fmaf(dec_w[d], er[d], s);
        }
        #pragma unroll
        for (int off = 16; off >= 1; off >>= 1)
            s += __shfl_down_sync(FULLM, s, off);
        if (lane == 0) g_score[code] = s;
    }
}

// ======== kernel 2 (k_ab): block = interval, thread = code, coalesced w2t stream ====
// Activity folded into pre-zeroed multipliers: fmaf(v,0,A)==A exactly, so the
// j-ascending direct sum is bit-identical to the previous kernels' tables.
__global__ void k_ab(const float* __restrict__ w1, const float* __restrict__ b1,
                     const float* __restrict__ b2)
{
    __shared__ float sbm[NH], swm[NH];
    int t = threadIdx.x;                 // 512 threads = code
    int i = blockIdx.x;                  // interval 0..128
    if (t < NH) {
        int r = g_actRank[t], s = g_sgn[t];
        bool act = (s > 0) ? (r < i) : (r >= i);
        sbm[t] = act ? b1[t] : 0.0f;
        swm[t] = act ? w1[t] : 0.0f;
    }
    __syncthreads();
    float A = b2[t], Bv = 0.0f;
    const float* wt = g_w2t + t;
    #pragma unroll 8
    for (int j = 0; j < NH; j++) {
        float v = wt[j * NCODES];        // coalesced: one 128B line per warp-LDG
        A  = fmaf(v, sbm[j], A);         // smem broadcast reads, conflict-free
        Bv = fmaf(v, swm[j], Bv);
    }
    g_A[i * NCODES + t] = A;
    g_B[i * NCODES + t] = Bv;
}

__device__ __forceinline__ int find_interval(const float* sk, float x) {
    int lo = 0, hi = NH;
    #pragma unroll
    for (int it = 0; it < 8; it++) {
        if (lo < hi) {
            int mid = (lo + hi) >> 1;
            if (sk[mid] <= x) lo = mid + 1; else hi = mid;
        }
    }
    return lo;   // number of kinks <= x, in [0,128]
}

// exact 512-line argmax from GLOBAL tables (rare fallback path in k_main)
__device__ __forceinline__ void scan512(const float* __restrict__ Ar,
                                        const float* __restrict__ Br,
                                        float xv, int lane, int& out_idx)
{
    float best = neg_inf(); int bi = 0;
    #pragma unroll
    for (int k = 0; k < 16; k++) {
        int c = lane + (k << 5);
        float v = fmaf(Br[c], xv, Ar[c]);
        if (v > best) { best = v; bi = c; }        // ascending c -> first-max per lane
    }
    #pragma unroll
    for (int off = 16; off >= 1; off >>= 1) {
        float ov = __shfl_down_sync(FULLM, best, off);
        int   oi = __shfl_down_sync(FULLM, bi,  off);
        if (ov > best || (ov == best && oi < bi)) { best = ov; bi = oi; }
    }
    out_idx = __shfl_sync(FULLM, bi, 0);           // jnp.argmax first-index semantics
}

// ======== kernel 3: coarse-to-fine classification with bisection, 1 coarse/warp ====
// Pairwise-dominance: within a kink-free span each line's dominance region is an
// interval -> equal endpoint argmax (+ same kink-interval) => constant throughout.
// Also emits the coarse-level table: clean + kink-free coarse cells resolve in smem
// inside k_main without touching the fine table.
__global__ void k_classify()
{
    __shared__ float sk[NH];
    int tid = threadIdx.x;
    if (tid < NH) sk[tid] = g_ksort[tid];
    __syncthreads();
    int wg = blockIdx.x * (blockDim.x >> 5) + (tid >> 5);
    if (wg >= NCOARSE) return;
    int lane = tid & 31;

    float a[16], b[16];
    int iload = -1;
    int ivCur = 0;

    auto evalEdge = [&](int e) -> int {          // warp-cooperative 512-line argmax
        float x = XMIN + (float)e * CW;
        int iv = find_interval(sk, x);           // warp-uniform
        if (iv != iload) {
            const float* Ar = g_A + iv * NCODES + lane;
            const float* Br = g_B + iv * NCODES + lane;
            #pragma unroll
            for (int k = 0; k < 16; k++) { a[k] = Ar[k << 5]; b[k] = Br[k << 5]; }
            iload = iv;
        }
        ivCur = iv;
        float best = neg_inf(); int bi = 0;
        #pragma unroll
        for (int k = 0; k < 16; k++) {
            float v = fmaf(b[k], x, a[k]);
            if (v > best) { best = v; bi = lane + (k << 5); }
        }
        #pragma unroll
        for (int off = 16; off >= 1; off >>= 1) {
            float ov = __shfl_down_sync(FULLM, best, off);
            int   oi = __shfl_down_sync(FULLM, bi,  off);
            if (ov > best || (ov == best && oi < bi)) { best = ov; bi = oi; }
        }
        return __shfl_sync(FULLM, bi, 0);
    };

    int loE = wg * 16, hiE = loE + 16;
    int argL = evalEdge(loE); int ivL = ivCur;
    int argR = evalEdge(hiE); int ivR = ivCur;

    // kink presence across this coarse cell's 16 fine cells
    unsigned char kn = (lane < 16) ? g_kinkNear[loE + lane] : 0;
    unsigned kmask = __ballot_sync(FULLM, kn != 0);
    bool anyKink = (kmask & 0xffffu) != 0;

    if (argL == argR && ivL == ivR) {
        // constant argmax; fine cells carry per-cell kink flags
        if (lane < 16)
            g_cellEnc[loE + lane] =
                (unsigned short)(argL | (kn ? 0x8000 : 0));
        if (lane == 0)
            g_coarseEnc[wg] =
                (unsigned short)(anyKink ? 0x8000 : argL);
        return;
    }
    if (lane == 0) g_coarseEnc[wg] = 0x8000;     // dirty: consult fine table

    // warp-uniform bisection stack (depth <= 4)
    auto fill = [&](int lo, int hi, int arg) {
        int cell = lo + lane;
        if (cell < hi)
            g_cellEnc[cell] =
                (unsigned short)(arg | (g_kinkNear[cell] ? 0x8000 : 0));
    };
    int sLo[8], sHi[8], sAL[8], sAH[8], sIL[8], sIH[8];
    sLo[0] = loE; sHi[0] = hiE; sAL[0] = argL; sAH[0] = argR;
    sIL[0] = ivL; sIH[0] = ivR;
    int sp = 1;
    while (sp) {
        sp--;
        int lo = sLo[sp], hi = sHi[sp];
        int aL = sAL[sp], aH = sAH[sp], iL = sIL[sp], iH = sIH[sp];
        if (aL == aH && iL == iH) { fill(lo, hi, aL); continue; }
        if (hi - lo == 1) {                      // boundary/kink inside: bad cell
            if (lane == 0)
                g_cellEnc[lo] = (unsigned short)(aL | 0x8000);
            continue;
        }
        int mid = (lo + hi) >> 1;
        int aM = evalEdge(mid);
        int iM = ivCur;
        sLo[sp] = lo;  sHi[sp] = mid; sAL[sp] = aL; sAH[sp] = aM;
        sIL[sp] = iL;  sIH[sp] = iM;  sp++;
        sLo[sp] = mid; sHi[sp] = hi;  sAL[sp] = aM; sAH[sp] = aH;
        sIL[sp] = iM;  sIH[sp] = iH;  sp++;
    }
}

// ======== kernel 4: smem coarse table fast path; fine L2 only for dirty cells ====
__global__ void k_main(const float* __restrict__ x_in, float* __restrict__ out,
                       int n, int write_idx)
{
    __shared__ unsigned short s_co[NCOARSE];     // 8 KB coarse table
    __shared__ float s_sc[NCODES];               // 2 KB score LUT
    __shared__ float s_sk[NH];
    int tid = threadIdx.x;                       // 256 threads
    {
        const uint4* src = (const uint4*)g_coarseEnc;
        uint4* dst = (uint4*)s_co;
        dst[tid] = src[tid];                     // 512 uint4 total
        dst[tid + 256] = src[tid + 256];
    }
    s_sc[tid] = g_score[tid];
    s_sc[tid + 256] = g_score[tid + 256];
    if (tid < NH) s_sk[tid] = g_ksort[tid];
    __syncthreads();
    float db = g_decb;

    int b = blockIdx.x * blockDim.x + tid;
    bool active = b < n;
    float x = 0.0f;
    if (active) x = x_in[b];

    int idx = 0;
    bool inR = active && x >= XMIN && x < XMAX;
    int g = 0;
    bool fine = false;
    if (inR) {
        g = (int)((x - XMIN) * INV_CW);
        if (g >= NCELLS) g = NCELLS - 1;
        unsigned ce = s_co[g >> 4];              // smem: no global dependency
        idx = ce & 511;
        fine = (ce & 0x8000u) != 0;
    }
    bool need = active && !inR;                  // out-of-range -> direct fallback
    if (fine) {                                  // rare: dirty coarse cell
        unsigned fe = g_cellEnc[g];              // random L2 load, <2% of threads
        idx = fe & 511;
        need = (fe & 0x8000u) != 0;
    }

    int lane = tid & 31;
    unsigned m = __ballot_sync(FULLM, need);
    while (m) {                                  // whole warp per fallback element
        int src = __ffs(m) - 1; m &= m - 1;
        float xb = __shfl_sync(FULLM, x, src);
        int ib = find_interval(s_sk, xb);        // warp-uniform
        int bi;
        scan512(g_A + ib * NCODES, g_B + ib * NCODES, xb, lane, bi);
        if (lane == src) idx = bi;
    }
    if (!active) return;
    out[b] = s_sc[idx] + db;
    if (write_idx) out[n + b] = (float)idx;
}

extern "C" void kernel_launch(void* const* d_in, const int* in_sizes, int n_in,
                              void* d_out, int out_size)
{
    const float* x     = (const float*)d_in[0];
    const float* w1    = (const float*)d_in[1];
    const float* b1    = (const float*)d_in[2];
    const float* w2    = (const float*)d_in[3];
    const float* b2    = (const float*)d_in[4];
    const float* emb   = (const float*)d_in[5];
    const float* dec_w = (const float*)d_in[6];
    const float* dec_b = (const float*)d_in[7];
    int n = in_sizes[0];
    float* out = (float*)d_out;

    k_pre<<<129, 256>>>(w1, b1, w2, emb, dec_w, dec_b);
    k_ab<<<129, 512>>>(w1, b1, b2);
    k_classify<<<NCOARSE / 8, 256>>>();
    int write_idx = (out_size >= 2 * n) ? 1 : 0;
    k_main<<<(n + 255) / 256, 256>>>(x, out, n, write_idx);
}